// round 5
// baseline (speedup 1.0000x reference)
#include <cuda_runtime.h>
#include <cstdint>

#define VQ_D   64
#define VQ_M   512
#define RPB    64          // rows per block
#define NTHR   512
#define ESTR   520         // e-tile row stride (floats), transposed [k][code]
#define XSTR   136         // x-tile row stride (floats), transposed + lane-duplicated [k][2*row]

// smem layout (floats): es[64*ESTR] | xs[64*XSTR] | xx[64] | keys(64 u64) | sidx(64 int) | lred(512 double)
#define SMEM_BYTES ((64*ESTR + 64*XSTR + 64)*4 + 64*8 + 64*4 + 512*8)

__device__ float  g_ee[VQ_M];
__device__ int    g_cnt[VQ_M];
__device__ double g_part[4096];

__device__ __forceinline__ unsigned int ford(float f) {
    unsigned int u = __float_as_uint(f);
    return (u & 0x80000000u) ? ~u : (u | 0x80000000u);
}

__device__ __forceinline__ void fma2(unsigned long long &d, unsigned long long a, unsigned long long b) {
    asm("fma.rn.f32x2 %0, %1, %2, %0;" : "+l"(d) : "l"(a), "l"(b));
}

// Zero counts + precompute ||e||^2 per code (sequential fp32, mirrors reference form)
__global__ void vq_init(const float* __restrict__ emb) {
    int t = blockIdx.x * blockDim.x + threadIdx.x;
    if (t < VQ_M) {
        g_cnt[t] = 0;
        const float* e = emb + t * VQ_D;
        float s = 0.f;
        for (int k = 0; k < VQ_D; ++k) s = fmaf(e[k], e[k], s);
        g_ee[t] = s;
    }
}

__global__ __launch_bounds__(NTHR, 1) void vq_main(
    const float* __restrict__ x, const float* __restrict__ emb,
    float* __restrict__ out, int nRows)
{
    extern __shared__ float smem[];
    float* es = smem;                          // 64 x ESTR
    float* xs = es + 64 * ESTR;                // 64 x XSTR (duplicated lanes)
    float* xx = xs + 64 * XSTR;                // 64
    unsigned long long* keys = (unsigned long long*)(xx + 64);   // 64
    int*    sidx = (int*)(keys + 64);                            // 64
    double* lred = (double*)(sidx + 64);                         // 512

    const int tid  = threadIdx.x;
    const int row0 = blockIdx.x * RPB;

    // ---- load embedding transposed: es[k][code] (conflict-free STS: codes consecutive per warp)
    {
        const float4* e4 = (const float4*)emb;
        int cl = tid & 31;         // code lane
        int kq = tid >> 5;         // 0..15 float4 index along D
        #pragma unroll
        for (int it = 0; it < 16; ++it) {
            int code = cl + (it << 5);
            float4 v = e4[code * (VQ_D/4) + kq];
            es[(4*kq+0)*ESTR + code] = v.x;
            es[(4*kq+1)*ESTR + code] = v.y;
            es[(4*kq+2)*ESTR + code] = v.z;
            es[(4*kq+3)*ESTR + code] = v.w;
        }
    }
    // ---- load x tile transposed with lane duplication: xs[k][2*row]=xs[k][2*row+1]=x[row][k]
    {
        const float4* x4 = (const float4*)x;
        int rl  = tid & 63;
        int kq0 = tid >> 6;        // 0..7
        #pragma unroll
        for (int it = 0; it < 2; ++it) {
            int kq = kq0 + (it << 3);
            float4 v = x4[(row0 + rl) * (VQ_D/4) + kq];
            *(float2*)&xs[(4*kq+0)*XSTR + 2*rl] = make_float2(v.x, v.x);
            *(float2*)&xs[(4*kq+1)*XSTR + 2*rl] = make_float2(v.y, v.y);
            *(float2*)&xs[(4*kq+2)*XSTR + 2*rl] = make_float2(v.z, v.z);
            *(float2*)&xs[(4*kq+3)*XSTR + 2*rl] = make_float2(v.w, v.w);
        }
    }
    __syncthreads();

    if (tid < RPB) {
        float s = 0.f;
        for (int k = 0; k < VQ_D; ++k) {
            float v = xs[k*XSTR + 2*tid];
            s = fmaf(v, v, s);
        }
        xx[tid]  = s;
        keys[tid] = ~0ull;
    }
    __syncthreads();

    const int c = tid & 63;        // 8 codes: 8c..8c+7
    const int r = tid >> 6;        // 8 rows:  8r..8r+7

    unsigned long long acc[8][4];  // lanes = (code 8c+2jp, 8c+2jp+1), index i = row 8r+i
    #pragma unroll
    for (int i = 0; i < 8; ++i)
        #pragma unroll
        for (int jp = 0; jp < 4; ++jp) acc[i][jp] = 0ull;

    const float* xp = xs + 16 * r;   // 16B-aligned
    const float* ep = es + 8 * c;    // 16B-aligned
    #pragma unroll 4
    for (int k = 0; k < VQ_D; ++k) {
        ulonglong2 xv0 = ((const ulonglong2*)xp)[0];  // dup(row 8r+0), dup(8r+1)
        ulonglong2 xv1 = ((const ulonglong2*)xp)[1];
        ulonglong2 xv2 = ((const ulonglong2*)xp)[2];
        ulonglong2 xv3 = ((const ulonglong2*)xp)[3];
        ulonglong2 ev0 = ((const ulonglong2*)ep)[0];  // (e[8c], e[8c+1]), (e[8c+2], e[8c+3])
        ulonglong2 ev1 = ((const ulonglong2*)ep)[1];
        unsigned long long e2[4] = {ev0.x, ev0.y, ev1.x, ev1.y};
        unsigned long long x8[8] = {xv0.x, xv0.y, xv1.x, xv1.y, xv2.x, xv2.y, xv3.x, xv3.y};
        #pragma unroll
        for (int i = 0; i < 8; ++i)
            #pragma unroll
            for (int jp = 0; jp < 4; ++jp)
                fma2(acc[i][jp], x8[i], e2[jp]);
        xp += XSTR; ep += ESTR;
    }

    // ---- score + argmin (mirror reference rounding: fl(fl(xx - 2p) + ee)), tie -> lowest code
    #pragma unroll
    for (int i = 0; i < 8; ++i) {
        int lrow = 8*r + i;
        float xxv = xx[lrow];
        unsigned long long best = ~0ull;
        #pragma unroll
        for (int jp = 0; jp < 4; ++jp) {
            unsigned long long a = acc[i][jp];
            float plo = __uint_as_float((unsigned int)a);
            float phi = __uint_as_float((unsigned int)(a >> 32));
            int clo = 8*c + 2*jp;
            float dlo = (xxv - 2.0f*plo) + g_ee[clo];
            float dhi = (xxv - 2.0f*phi) + g_ee[clo+1];
            unsigned long long klo = ((unsigned long long)ford(dlo) << 32) | (unsigned int)clo;
            unsigned long long khi = ((unsigned long long)ford(dhi) << 32) | (unsigned int)(clo+1);
            if (klo < best) best = klo;
            if (khi < best) best = khi;
        }
        atomicMin(&keys[lrow], best);
    }
    __syncthreads();

    if (tid < RPB) {
        int idx = (int)(keys[tid] & 0xffffffffull);
        sidx[tid] = idx;
        atomicAdd(&g_cnt[idx], 1);
    }
    __syncthreads();

    // ---- straight-through output + loss partial (fp32 elementwise like reference, double accumulate)
    double ls = 0.0;
    {
        int orow = tid >> 3;
        int kq   = (tid & 7) * 2;        // float4 index, 2 per thread
        int grow = row0 + orow;
        int idx  = sidx[orow];
        const float4* x4 = (const float4*)x;
        const float4* e4 = (const float4*)emb;
        float4* o4 = (float4*)out;
        #pragma unroll
        for (int h = 0; h < 2; ++h) {
            float4 xa = x4[grow * (VQ_D/4) + kq + h];
            float4 ea = e4[idx  * (VQ_D/4) + kq + h];
            float4 st;
            st.x = xa.x + (ea.x - xa.x);
            st.y = xa.y + (ea.y - xa.y);
            st.z = xa.z + (ea.z - xa.z);
            st.w = xa.w + (ea.w - xa.w);
            o4[grow * (VQ_D/4) + kq + h] = st;
            float d0 = xa.x - ea.x; float d1 = xa.y - ea.y;
            float d2 = xa.z - ea.z; float d3 = xa.w - ea.w;
            ls += (double)(d0*d0) + (double)(d1*d1) + (double)(d2*d2) + (double)(d3*d3);
        }
    }
    lred[tid] = ls;
    __syncthreads();
    #pragma unroll
    for (int s = 256; s > 0; s >>= 1) {
        if (tid < s) lred[tid] += lred[tid + s];
        __syncthreads();
    }
    if (tid == 0) g_part[blockIdx.x] = lred[0];
}

__global__ __launch_bounds__(512) void vq_final(float* __restrict__ out, int nElems,
                                                int nBlocks, float invRows)
{
    __shared__ double sd[512];
    int t = threadIdx.x;
    double s = 0.0;
    for (int b = t; b < nBlocks; b += 512) s += g_part[b];   // fixed order -> deterministic
    sd[t] = s; __syncthreads();
    for (int h = 256; h > 0; h >>= 1) { if (t < h) sd[t] += sd[t+h]; __syncthreads(); }
    double lossSum = sd[0];
    __syncthreads();

    float p = (float)g_cnt[t] * invRows;          // exact: invRows is power of 2
    float term = p * logf(p + 1e-10f);
    sd[t] = (double)term; __syncthreads();
    for (int h = 256; h > 0; h >>= 1) { if (t < h) sd[t] += sd[t+h]; __syncthreads(); }

    if (t == 0) {
        float mean = (float)(lossSum / (double)nElems);
        out[nElems]     = 0.25f * mean;           // commitment loss
        out[nElems + 1] = expf(-(float)sd[0]);    // perplexity
    }
}

extern "C" void kernel_launch(void* const* d_in, const int* in_sizes, int n_in,
                              void* d_out, int out_size)
{
    const float* x   = (const float*)d_in[0];
    const float* emb = (const float*)d_in[1];
    int nElems = in_sizes[0];
    if (n_in >= 2 && in_sizes[0] < in_sizes[1]) {   // defensive: x is the big tensor
        x = (const float*)d_in[1];
        emb = (const float*)d_in[0];
        nElems = in_sizes[1];
    }
    float* out = (float*)d_out;
    int nRows   = nElems / VQ_D;      // 131072
    int nBlocks = nRows / RPB;        // 2048

    cudaFuncSetAttribute(vq_main, cudaFuncAttributeMaxDynamicSharedMemorySize, SMEM_BYTES);

    vq_init<<<1, VQ_M>>>(emb);
    vq_main<<<nBlocks, NTHR, SMEM_BYTES>>>(x, emb, out, nRows);
    vq_final<<<1, 512>>>(out, nElems, nBlocks, 1.0f / (float)nRows);
}

// round 6
// speedup vs baseline: 1.1868x; 1.1868x over previous
#include <cuda_runtime.h>
#include <cstdint>

#define VQ_D   64
#define VQ_M   512
#define RPB    64          // rows per block
#define NTHR   512
#define ESTR   520         // e-tile row stride (floats), transposed [k][code]
#define XSTR   136         // x-tile row stride (floats), transposed + lane-duplicated [k][2*row]

// smem floats: es[64*ESTR] | xs[64*XSTR] | xx[64] | see[512] ; then keys(64 u64) | sidx(64 i32) | lred(16 f64)
#define SMEM_FLOATS (64*ESTR + 64*XSTR + 64 + 512)
#define SMEM_BYTES  (SMEM_FLOATS*4 + 64*8 + 64*4 + 16*8)

__device__ float  g_ee[VQ_M];
__device__ int    g_cnt[VQ_M];
__device__ double g_part[4096];

__device__ __forceinline__ unsigned int ford(float f) {
    unsigned int u = __float_as_uint(f);
    return (u & 0x80000000u) ? ~u : (u | 0x80000000u);
}

__device__ __forceinline__ void fma2(unsigned long long &d, unsigned long long a, unsigned long long b) {
    asm("fma.rn.f32x2 %0, %1, %2, %0;" : "+l"(d) : "l"(a), "l"(b));
}

// Zero counts + precompute ||e||^2 per code (sequential fp32 order preserved), 8 blocks x 64 thr
__global__ void vq_init(const float* __restrict__ emb) {
    int t = blockIdx.x * 64 + threadIdx.x;
    if (t < VQ_M) {
        g_cnt[t] = 0;
        const float4* e4 = (const float4*)(emb + t * VQ_D);
        float s = 0.f;
        #pragma unroll
        for (int q = 0; q < VQ_D/4; ++q) {
            float4 v = e4[q];
            s = fmaf(v.x, v.x, s);
            s = fmaf(v.y, v.y, s);
            s = fmaf(v.z, v.z, s);
            s = fmaf(v.w, v.w, s);
        }
        g_ee[t] = s;
    }
}

__global__ __launch_bounds__(NTHR, 1) void vq_main(
    const float* __restrict__ x, const float* __restrict__ emb,
    float* __restrict__ out, int nRows)
{
    extern __shared__ float smem[];
    float* es  = smem;                          // 64 x ESTR
    float* xs  = es + 64 * ESTR;                // 64 x XSTR (duplicated lanes)
    float* xx  = xs + 64 * XSTR;                // 64
    float* see = xx + 64;                       // 512 (||e||^2 staged)
    unsigned long long* keys = (unsigned long long*)(see + 512);  // 64
    int*    sidx = (int*)(keys + 64);                             // 64
    double* lred = (double*)(sidx + 64);                          // 16

    const int tid  = threadIdx.x;
    const int lane = tid & 31;
    const int row0 = blockIdx.x * RPB;

    // ---- load embedding transposed: es[k][code] (conflict-free STS: codes consecutive per warp)
    {
        const float4* e4 = (const float4*)emb;
        int cl = tid & 31;         // code lane
        int kq = tid >> 5;         // 0..15 float4 index along D
        #pragma unroll
        for (int it = 0; it < 16; ++it) {
            int code = cl + (it << 5);
            float4 v = e4[code * (VQ_D/4) + kq];
            es[(4*kq+0)*ESTR + code] = v.x;
            es[(4*kq+1)*ESTR + code] = v.y;
            es[(4*kq+2)*ESTR + code] = v.z;
            es[(4*kq+3)*ESTR + code] = v.w;
        }
    }
    // ---- stage ||e||^2
    if (tid < VQ_M) see[tid] = g_ee[tid];
    // ---- load x tile transposed with lane duplication: xs[k][2*row]=xs[k][2*row+1]=x[row][k]
    {
        const float4* x4 = (const float4*)x;
        int rl  = tid & 63;
        int kq0 = tid >> 6;        // 0..7
        #pragma unroll
        for (int it = 0; it < 2; ++it) {
            int kq = kq0 + (it << 3);
            float4 v = x4[(row0 + rl) * (VQ_D/4) + kq];
            *(float2*)&xs[(4*kq+0)*XSTR + 2*rl] = make_float2(v.x, v.x);
            *(float2*)&xs[(4*kq+1)*XSTR + 2*rl] = make_float2(v.y, v.y);
            *(float2*)&xs[(4*kq+2)*XSTR + 2*rl] = make_float2(v.z, v.z);
            *(float2*)&xs[(4*kq+3)*XSTR + 2*rl] = make_float2(v.w, v.w);
        }
    }
    __syncthreads();

    if (tid < RPB) {
        float s = 0.f;
        for (int k = 0; k < VQ_D; ++k) {
            float v = xs[k*XSTR + 2*tid];
            s = fmaf(v, v, s);
        }
        xx[tid]   = s;
        keys[tid] = ~0ull;
    }
    __syncthreads();

    const int c = tid & 63;        // code pairs: (2c, 2c+1) + 128*jp
    const int r = tid >> 6;        // rows 8r..8r+7 (uniform per warp)

    unsigned long long acc[8][4];
    #pragma unroll
    for (int i = 0; i < 8; ++i)
        #pragma unroll
        for (int jp = 0; jp < 4; ++jp) acc[i][jp] = 0ull;

    const float* xp = xs + 16 * r;     // broadcast (warp-uniform), 16B aligned
    const float* ep = es + 2 * c;      // 8B lane stride -> conflict-free LDS.64
    #pragma unroll 2
    for (int k = 0; k < VQ_D; ++k) {
        ulonglong2 xv0 = ((const ulonglong2*)xp)[0];
        ulonglong2 xv1 = ((const ulonglong2*)xp)[1];
        ulonglong2 xv2 = ((const ulonglong2*)xp)[2];
        ulonglong2 xv3 = ((const ulonglong2*)xp)[3];
        unsigned long long e2[4];
        e2[0] = *(const unsigned long long*)(ep + 0);
        e2[1] = *(const unsigned long long*)(ep + 128);
        e2[2] = *(const unsigned long long*)(ep + 256);
        e2[3] = *(const unsigned long long*)(ep + 384);
        unsigned long long x8[8] = {xv0.x, xv0.y, xv1.x, xv1.y, xv2.x, xv2.y, xv3.x, xv3.y};
        #pragma unroll
        for (int i = 0; i < 8; ++i)
            #pragma unroll
            for (int jp = 0; jp < 4; ++jp)
                fma2(acc[i][jp], x8[i], e2[jp]);
        xp += XSTR; ep += ESTR;
    }

    // ---- score + argmin. Reference rounding: fl(fl(xx - 2p) + ee); tie -> lowest code.
    // Butterfly-reduce each row's best across the warp, then one spread atomic per warp.
    unsigned long long rowbest = ~0ull;
    #pragma unroll
    for (int i = 0; i < 8; ++i) {
        int lrow = 8*r + i;
        float xxv = xx[lrow];
        unsigned long long best = ~0ull;
        #pragma unroll
        for (int jp = 0; jp < 4; ++jp) {
            unsigned long long a = acc[i][jp];
            float plo = __uint_as_float((unsigned int)a);
            float phi = __uint_as_float((unsigned int)(a >> 32));
            int clo = 2*c + 128*jp;
            float2 ee2 = *(const float2*)&see[clo];
            float dlo = (xxv - 2.0f*plo) + ee2.x;
            float dhi = (xxv - 2.0f*phi) + ee2.y;
            unsigned long long klo = ((unsigned long long)ford(dlo) << 32) | (unsigned int)clo;
            unsigned long long khi = ((unsigned long long)ford(dhi) << 32) | (unsigned int)(clo+1);
            if (klo < best) best = klo;
            if (khi < best) best = khi;
        }
        #pragma unroll
        for (int m = 16; m > 0; m >>= 1) {
            unsigned long long o = __shfl_xor_sync(0xffffffffu, best, m);
            if (o < best) best = o;
        }
        if (lane == i) rowbest = best;
    }
    if (lane < 8) atomicMin(&keys[8*r + lane], rowbest);   // 2 warps contend per row only
    __syncthreads();

    if (tid < RPB) {
        int idx = (int)(keys[tid] & 0xffffffffull);
        sidx[tid] = idx;
        atomicAdd(&g_cnt[idx], 1);
    }
    __syncthreads();

    // ---- straight-through output + loss partial (fp32 elementwise, fp64 accumulate)
    double ls = 0.0;
    {
        int orow = tid >> 3;
        int kq   = (tid & 7) * 2;
        int grow = row0 + orow;
        int idx  = sidx[orow];
        const float4* x4 = (const float4*)x;
        const float4* e4 = (const float4*)emb;
        float4* o4 = (float4*)out;
        #pragma unroll
        for (int h = 0; h < 2; ++h) {
            float4 xa = x4[grow * (VQ_D/4) + kq + h];
            float4 ea = e4[idx  * (VQ_D/4) + kq + h];
            float4 st;
            st.x = xa.x + (ea.x - xa.x);
            st.y = xa.y + (ea.y - xa.y);
            st.z = xa.z + (ea.z - xa.z);
            st.w = xa.w + (ea.w - xa.w);
            o4[grow * (VQ_D/4) + kq + h] = st;
            float d0 = xa.x - ea.x; float d1 = xa.y - ea.y;
            float d2 = xa.z - ea.z; float d3 = xa.w - ea.w;
            ls += (double)(d0*d0) + (double)(d1*d1) + (double)(d2*d2) + (double)(d3*d3);
        }
    }
    #pragma unroll
    for (int m = 16; m > 0; m >>= 1)
        ls += __shfl_xor_sync(0xffffffffu, ls, m);
    if (lane == 0) lred[tid >> 5] = ls;
    __syncthreads();
    if (tid < 32) {
        double s = (tid < 16) ? lred[tid] : 0.0;
        #pragma unroll
        for (int m = 8; m > 0; m >>= 1)
            s += __shfl_xor_sync(0xffffffffu, s, m);
        if (tid == 0) g_part[blockIdx.x] = s;
    }
}

__global__ __launch_bounds__(512) void vq_final(float* __restrict__ out, int nElems,
                                                int nBlocks, float invRows)
{
    __shared__ double sd[512];
    int t = threadIdx.x;
    double s = 0.0;
    for (int b = t; b < nBlocks; b += 512) s += g_part[b];   // fixed order -> deterministic
    sd[t] = s; __syncthreads();
    for (int h = 256; h > 0; h >>= 1) { if (t < h) sd[t] += sd[t+h]; __syncthreads(); }
    double lossSum = sd[0];
    __syncthreads();

    float p = (float)g_cnt[t] * invRows;          // exact: invRows is power of 2
    float term = p * logf(p + 1e-10f);
    sd[t] = (double)term; __syncthreads();
    for (int h = 256; h > 0; h >>= 1) { if (t < h) sd[t] += sd[t+h]; __syncthreads(); }

    if (t == 0) {
        float mean = (float)(lossSum / (double)nElems);
        out[nElems]     = 0.25f * mean;           // commitment loss
        out[nElems + 1] = expf(-(float)sd[0]);    // perplexity
    }
}

extern "C" void kernel_launch(void* const* d_in, const int* in_sizes, int n_in,
                              void* d_out, int out_size)
{
    const float* x   = (const float*)d_in[0];
    const float* emb = (const float*)d_in[1];
    int nElems = in_sizes[0];
    if (n_in >= 2 && in_sizes[0] < in_sizes[1]) {   // defensive: x is the big tensor
        x = (const float*)d_in[1];
        emb = (const float*)d_in[0];
        nElems = in_sizes[1];
    }
    float* out = (float*)d_out;
    int nRows   = nElems / VQ_D;      // 131072
    int nBlocks = nRows / RPB;        // 2048

    cudaFuncSetAttribute(vq_main, cudaFuncAttributeMaxDynamicSharedMemorySize, SMEM_BYTES);

    vq_init<<<8, 64>>>(emb);
    vq_main<<<nBlocks, NTHR, SMEM_BYTES>>>(x, emb, out, nRows);
    vq_final<<<1, 512>>>(out, nElems, nBlocks, 1.0f / (float)nRows);
}